// round 9
// baseline (speedup 1.0000x reference)
#include <cuda_runtime.h>
#include <cuda_fp16.h>
#include <cuda_bf16.h>
#include <cstdint>

#define BB 16
#define N1 4096
#define N2 1024
#define C1 128
#define C2 256
#define DIN 384
#define DOUT 256
#define NQ (BB * N1)

// ---------------- device scratch ----------------
__device__ __align__(16) __half g_X[(size_t)NQ * DIN];
__device__ __align__(16) __half g_H[(size_t)NQ * DOUT];
__device__ __align__(16) __half g_W1T[DOUT * DIN];
__device__ __align__(16) __half g_W2T[DOUT * DOUT];
__device__ __align__(16) __half g_feat2h[(size_t)BB * N2 * C2];

// ---------------- PTX helpers (portable, OK on compute_103) ----------------
__device__ __forceinline__ uint32_t smem_u32(const void* p) {
    uint32_t a;
    asm("{ .reg .u64 t; cvta.to.shared.u64 t, %1; cvt.u32.u64 %0, t; }" : "=r"(a) : "l"(p));
    return a;
}
#define CP_ASYNC16(dst, src) \
    asm volatile("cp.async.cg.shared.global [%0], [%1], 16;" :: "r"(dst), "l"(src))
#define CP_COMMIT() asm volatile("cp.async.commit_group;" ::: "memory")
#define CP_WAIT(n)  asm volatile("cp.async.wait_group %0;" :: "n"(n) : "memory")

__device__ __forceinline__ void ldmatrix_x4(uint32_t* r, uint32_t addr) {
    asm volatile("ldmatrix.sync.aligned.m8n8.x4.shared.b16 {%0,%1,%2,%3}, [%4];"
                 : "=r"(r[0]), "=r"(r[1]), "=r"(r[2]), "=r"(r[3]) : "r"(addr));
}
__device__ __forceinline__ void mma16816(float* d, const uint32_t* a, const uint32_t* b) {
    asm volatile(
        "mma.sync.aligned.m16n8k16.row.col.f32.f16.f16.f32 "
        "{%0,%1,%2,%3}, {%4,%5,%6,%7}, {%8,%9}, {%0,%1,%2,%3};"
        : "+f"(d[0]), "+f"(d[1]), "+f"(d[2]), "+f"(d[3])
        : "r"(a[0]), "r"(a[1]), "r"(a[2]), "r"(a[3]), "r"(b[0]), "r"(b[1]));
}
#define SWZ(bo) ((bo) ^ (((bo) >> 3) & 0x70))

// exact top-3 merge of two sorted triples across shuffle distance dlt
__device__ __forceinline__ void merge3(float& b0, float& b1, float& b2,
                                       int& i0, int& i1, int& i2, int dlt) {
    float c0 = __shfl_xor_sync(0xffffffffu, b0, dlt);
    float c1 = __shfl_xor_sync(0xffffffffu, b1, dlt);
    float c2 = __shfl_xor_sync(0xffffffffu, b2, dlt);
    int k0 = __shfl_xor_sync(0xffffffffu, i0, dlt);
    int k1 = __shfl_xor_sync(0xffffffffu, i1, dlt);
    int k2 = __shfl_xor_sync(0xffffffffu, i2, dlt);
    if (c0 < b0) {   // full triple swap keeps b-triple sorted
        float tf; int ti;
        tf = b0; b0 = c0; c0 = tf; ti = i0; i0 = k0; k0 = ti;
        tf = b1; b1 = c1; c1 = tf; ti = i1; i1 = k1; k1 = ti;
        tf = b2; b2 = c2; c2 = tf; ti = i2; i2 = k2; k2 = ti;
    }
    if (c0 < b1) {
        if (b1 < c1) { b2 = b1; i2 = i1; } else { b2 = c1; i2 = k1; }
        b1 = c0; i1 = k0;
    } else if (c0 < b2) { b2 = c0; i2 = k0; }
    (void)c2; (void)k2;  // partner's 3rd can be at best 4th after the swap
}

// ---------------------------------------------------------------------------
// Kernel A: fused 3-NN + interpolation + concat. One block = 64 queries.
// knn: 2 queries/thread share each candidate load; 8 subs x 128 candidates;
// selection key val = |p|^2 - 2 q.p (exact fp32); winners' distances
// recomputed in the reference (x1-x2)^2 form for the weights.
// ---------------------------------------------------------------------------
__global__ __launch_bounds__(256) void knn_interp_kernel(
    const float* __restrict__ xyz1, const float* __restrict__ xyz2,
    const float* __restrict__ feat1) {
    __shared__ float4 pts[N2];
    __shared__ int   sidx[64 * 3];
    __shared__ float swt[64 * 3];

    const int qb = blockIdx.x * 64;
    const int b = qb >> 12;
    const float* x2 = xyz2 + (size_t)b * N2 * 3;
    for (int j = threadIdx.x; j < N2; j += 256) {
        float x = x2[3 * j], y = x2[3 * j + 1], z = x2[3 * j + 2];
        pts[j] = make_float4(x, y, z, x * x + y * y + z * z);
    }
    __syncthreads();

    // ---- phase 1: knn ----
    {
        const int pr = threadIdx.x >> 3;   // 0..31 query pair
        const int sub = threadIdx.x & 7;   // 0..7
        const int qA = qb + pr * 2, qB = qA + 1;
        const float qx0 = xyz1[3 * qA], qy0 = xyz1[3 * qA + 1], qz0 = xyz1[3 * qA + 2];
        const float qx1 = xyz1[3 * qB], qy1 = xyz1[3 * qB + 1], qz1 = xyz1[3 * qB + 2];
        const float ax0 = -2.0f * qx0, ay0 = -2.0f * qy0, az0 = -2.0f * qz0;
        const float ax1 = -2.0f * qx1, ay1 = -2.0f * qy1, az1 = -2.0f * qz1;

        float A0 = 3.4e38f, A1 = 3.4e38f, A2 = 3.4e38f;
        float B0 = 3.4e38f, B1 = 3.4e38f, B2 = 3.4e38f;
        int ia0 = 0, ia1 = 0, ia2 = 0, ib0 = 0, ib1 = 0, ib2 = 0;
#pragma unroll 8
        for (int i = 0; i < 128; i++) {
            const int j = sub + 8 * i;
            float4 p = pts[j];
            float v0 = fmaf(ax0, p.x, fmaf(ay0, p.y, fmaf(az0, p.z, p.w)));
            float v1 = fmaf(ax1, p.x, fmaf(ay1, p.y, fmaf(az1, p.z, p.w)));
            if (v0 < A2) {
                if (v0 < A1) {
                    if (v0 < A0) { A2 = A1; ia2 = ia1; A1 = A0; ia1 = ia0; A0 = v0; ia0 = j; }
                    else         { A2 = A1; ia2 = ia1; A1 = v0; ia1 = j; }
                } else { A2 = v0; ia2 = j; }
            }
            if (v1 < B2) {
                if (v1 < B1) {
                    if (v1 < B0) { B2 = B1; ib2 = ib1; B1 = B0; ib1 = ib0; B0 = v1; ib0 = j; }
                    else         { B2 = B1; ib2 = ib1; B1 = v1; ib1 = j; }
                } else { B2 = v1; ib2 = j; }
            }
        }
#pragma unroll
        for (int dlt = 1; dlt <= 4; dlt <<= 1) {
            merge3(A0, A1, A2, ia0, ia1, ia2, dlt);
            merge3(B0, B1, B2, ib0, ib1, ib2, dlt);
        }
        if (sub == 0) {
            // exact reference-form distances for the winners
            float4 p; float dx, dy, dz;
            const int lqA = pr * 2, lqB = lqA + 1;
            p = pts[ia0]; dx = qx0 - p.x; dy = qy0 - p.y; dz = qz0 - p.z;
            float d0 = fmaxf(dx * dx + dy * dy + dz * dz, 1e-10f);
            p = pts[ia1]; dx = qx0 - p.x; dy = qy0 - p.y; dz = qz0 - p.z;
            float d1 = fmaxf(dx * dx + dy * dy + dz * dz, 1e-10f);
            p = pts[ia2]; dx = qx0 - p.x; dy = qy0 - p.y; dz = qz0 - p.z;
            float d2 = fmaxf(dx * dx + dy * dy + dz * dz, 1e-10f);
            float w0 = 1.0f / d0, w1 = 1.0f / d1, w2 = 1.0f / d2;
            float inv = 1.0f / (w0 + w1 + w2);
            sidx[lqA * 3] = ia0; sidx[lqA * 3 + 1] = ia1; sidx[lqA * 3 + 2] = ia2;
            swt[lqA * 3] = w0 * inv; swt[lqA * 3 + 1] = w1 * inv; swt[lqA * 3 + 2] = w2 * inv;

            p = pts[ib0]; dx = qx1 - p.x; dy = qy1 - p.y; dz = qz1 - p.z;
            d0 = fmaxf(dx * dx + dy * dy + dz * dz, 1e-10f);
            p = pts[ib1]; dx = qx1 - p.x; dy = qy1 - p.y; dz = qz1 - p.z;
            d1 = fmaxf(dx * dx + dy * dy + dz * dz, 1e-10f);
            p = pts[ib2]; dx = qx1 - p.x; dy = qy1 - p.y; dz = qz1 - p.z;
            d2 = fmaxf(dx * dx + dy * dy + dz * dz, 1e-10f);
            w0 = 1.0f / d0; w1 = 1.0f / d1; w2 = 1.0f / d2;
            inv = 1.0f / (w0 + w1 + w2);
            sidx[lqB * 3] = ib0; sidx[lqB * 3 + 1] = ib1; sidx[lqB * 3 + 2] = ib2;
            swt[lqB * 3] = w0 * inv; swt[lqB * 3 + 1] = w1 * inv; swt[lqB * 3 + 2] = w2 * inv;
        }
    }
    __syncthreads();

    // ---- phase 2: gather + concat (warp per query, 8 iterations) ----
    const int wq = threadIdx.x >> 5;
    const int lane = threadIdx.x & 31;
    const __half* f2 = g_feat2h + (size_t)b * N2 * C2;
#pragma unroll
    for (int it = 0; it < 8; it++) {
        const int lq = it * 8 + wq;
        const int q = qb + lq;
        const int i0 = sidx[lq * 3], i1 = sidx[lq * 3 + 1], i2 = sidx[lq * 3 + 2];
        const float w0 = swt[lq * 3], w1 = swt[lq * 3 + 1], w2 = swt[lq * 3 + 2];

        const uint4 v0 = ((const uint4*)(f2 + (size_t)i0 * C2))[lane];
        const uint4 v1 = ((const uint4*)(f2 + (size_t)i1 * C2))[lane];
        const uint4 v2 = ((const uint4*)(f2 + (size_t)i2 * C2))[lane];
        const __half2* h0 = (const __half2*)&v0;
        const __half2* h1 = (const __half2*)&v1;
        const __half2* h2 = (const __half2*)&v2;
        uint4 ov;
        __half2* oh = (__half2*)&ov;
#pragma unroll
        for (int k = 0; k < 4; k++) {
            float2 a = __half22float2(h0[k]);
            float2 d = __half22float2(h1[k]);
            float2 e = __half22float2(h2[k]);
            oh[k] = __floats2half2_rn(w0 * a.x + w1 * d.x + w2 * e.x,
                                      w0 * a.y + w1 * d.y + w2 * e.y);
        }
        __half* x = g_X + (size_t)q * DIN;
        ((uint4*)x)[lane] = ov;

        float4 f = ((const float4*)(feat1 + (size_t)q * C1))[lane];
        __half2 f0 = __floats2half2_rn(f.x, f.y);
        __half2 f1h = __floats2half2_rn(f.z, f.w);
        *(__half2*)(x + C2 + lane * 4) = f0;
        *(__half2*)(x + C2 + lane * 4 + 2) = f1h;
    }
}

// ---------------------------------------------------------------------------
// Kernel B: feat2 -> fp16 AND W1/W2 transpose+fp16, one launch.
// ---------------------------------------------------------------------------
#define F2H_BLOCKS 4096
#define PREPW_BLOCKS 640

__global__ void prep_all(const float* __restrict__ feat2,
                         const float* __restrict__ W1,
                         const float* __restrict__ W2) {
    if (blockIdx.x < F2H_BLOCKS) {
        const size_t i = ((size_t)blockIdx.x * 256 + threadIdx.x) * 4;
        float4 v = *(const float4*)(feat2 + i);
        __half2 h0 = __floats2half2_rn(v.x, v.y);
        __half2 h1 = __floats2half2_rn(v.z, v.w);
        uint2 o;
        o.x = *(const uint32_t*)&h0;
        o.y = *(const uint32_t*)&h1;
        *(uint2*)(g_feat2h + i) = o;
    } else {
        int i = (blockIdx.x - F2H_BLOCKS) * 256 + threadIdx.x;
        if (i < DIN * DOUT) {
            int k = i / DOUT, n = i % DOUT;
            g_W1T[n * DIN + k] = __float2half(W1[i]);
        } else {
            int j = i - DIN * DOUT;
            int k = j / DOUT, n = j % DOUT;
            g_W2T[n * DOUT + k] = __float2half(W2[j]);
        }
    }
}

// ---------------------------------------------------------------------------
// HGEMM: C[M,256] = relu(A[M,K] @ W + bias). CTA tile 128x128, BK=64,
// 3-stage cp.async pipeline + SOFTWARE-PIPELINED FRAGMENTS: ldmatrix for
// ks+1 issued while ks's 16 MMAs execute (double-buffered af/bf regs).
// ---------------------------------------------------------------------------
#define HGEMM_SMEM (3 * 32768)

template<int K, bool WRITE_H>
__global__ __launch_bounds__(256, 2) void hgemm(
    const __half* __restrict__ A, const __half* __restrict__ Bt,
    const float* __restrict__ bias,
    __half* __restrict__ outH, float* __restrict__ outF) {
    constexpr int NC = K / 64;
    extern __shared__ char smem[];
    const uint32_t sb = smem_u32(smem);
    const int tid = threadIdx.x;
    const int w = tid >> 5, lane = tid & 31;
    const int wy = w >> 2, wx = w & 3;
    const int mblk = blockIdx.y * 128, nblk = blockIdx.x * 128;

    const char* Abase = (const char*)(A + (size_t)mblk * K);
    const char* Bbase = (const char*)(Bt + (size_t)nblk * K);
    const int row_l = tid >> 3;
    const int ch_l = tid & 7;

    float acc[4][4][4];
#pragma unroll
    for (int i = 0; i < 4; i++)
#pragma unroll
        for (int j = 0; j < 4; j++)
#pragma unroll
            for (int k = 0; k < 4; k++) acc[i][j][k] = 0.0f;

    auto issue = [&](int c) {
        const uint32_t base = sb + (uint32_t)(c % 3) * 32768u;
        const char* ag = Abase + (size_t)c * 128;
        const char* bg = Bbase + (size_t)c * 128;
#pragma unroll
        for (int rr = 0; rr < 4; rr++) {
            const int row = row_l + rr * 32;
            const uint32_t off = (uint32_t)(row * 128 + ch_l * 16);
            const uint32_t d = base + SWZ(off);
            CP_ASYNC16(d, ag + (size_t)row * (K * 2) + ch_l * 16);
            CP_ASYNC16(d + 16384, bg + (size_t)row * (K * 2) + ch_l * 16);
        }
        CP_COMMIT();
    };

    uint32_t af[2][4][4];
    uint32_t bf[2][4][2];
    auto load_frags = [&](int ks, int pb, uint32_t abase, uint32_t bbase) {
#pragma unroll
        for (int mt = 0; mt < 4; mt++) {
            const int row = wy * 64 + mt * 16 + ((lane >> 3) & 1) * 8 + (lane & 7);
            const int ch = ks * 2 + (lane >> 4);
            ldmatrix_x4(af[pb][mt], abase + SWZ((uint32_t)(row * 128 + ch * 16)));
        }
#pragma unroll
        for (int p = 0; p < 2; p++) {
            const int t = lane >> 3;
            const int nrow = wx * 32 + (2 * p + (t >> 1)) * 8 + (lane & 7);
            const int ch = ks * 2 + (t & 1);
            uint32_t r[4];
            ldmatrix_x4(r, bbase + SWZ((uint32_t)(nrow * 128 + ch * 16)));
            bf[pb][2 * p][0] = r[0]; bf[pb][2 * p][1] = r[1];
            bf[pb][2 * p + 1][0] = r[2]; bf[pb][2 * p + 1][1] = r[3];
        }
    };

    issue(0);
    issue(1);
#pragma unroll
    for (int c = 0; c < NC; c++) {
        if (c + 1 < NC) { CP_WAIT(1); } else { CP_WAIT(0); }
        __syncthreads();
        const uint32_t abase = sb + (uint32_t)(c % 3) * 32768u;
        const uint32_t bbase = abase + 16384u;
        load_frags(0, 0, abase, bbase);
#pragma unroll
        for (int ks = 0; ks < 4; ks++) {
            if (ks < 3) load_frags(ks + 1, (ks + 1) & 1, abase, bbase);
            const int pb = ks & 1;
#pragma unroll
            for (int mt = 0; mt < 4; mt++)
#pragma unroll
                for (int nt = 0; nt < 4; nt++)
                    mma16816(acc[mt][nt], af[pb][mt], bf[pb][nt]);
        }
        if (c + 2 < NC) issue(c + 2);
    }

#pragma unroll
    for (int mt = 0; mt < 4; mt++) {
#pragma unroll
        for (int nt = 0; nt < 4; nt++) {
            const int row0 = mblk + wy * 64 + mt * 16 + (lane >> 2);
            const int col = nblk + wx * 32 + nt * 8 + 2 * (lane & 3);
            const float bz0 = bias[col], bz1 = bias[col + 1];
            float v00 = fmaxf(acc[mt][nt][0] + bz0, 0.0f);
            float v01 = fmaxf(acc[mt][nt][1] + bz1, 0.0f);
            float v10 = fmaxf(acc[mt][nt][2] + bz0, 0.0f);
            float v11 = fmaxf(acc[mt][nt][3] + bz1, 0.0f);
            if constexpr (WRITE_H) {
                *(__half2*)(outH + (size_t)row0 * 256 + col) = __floats2half2_rn(v00, v01);
                *(__half2*)(outH + (size_t)(row0 + 8) * 256 + col) = __floats2half2_rn(v10, v11);
            } else {
                float2 o0; o0.x = v00; o0.y = v01;
                float2 o1; o1.x = v10; o1.y = v11;
                *(float2*)(outF + (size_t)row0 * 256 + col) = o0;
                *(float2*)(outF + (size_t)(row0 + 8) * 256 + col) = o1;
            }
        }
    }
}

// ---------------------------------------------------------------------------
extern "C" void kernel_launch(void* const* d_in, const int* in_sizes, int n_in,
                              void* d_out, int out_size) {
    const float* xyz1  = (const float*)d_in[0];
    const float* feat1 = (const float*)d_in[1];
    const float* xyz2  = (const float*)d_in[2];
    const float* feat2 = (const float*)d_in[3];
    const float* W1    = (const float*)d_in[4];
    const float* b1    = (const float*)d_in[5];
    const float* W2    = (const float*)d_in[6];
    const float* b2    = (const float*)d_in[7];
    float* out = (float*)d_out;

    __half *X, *H, *W1T, *W2T;
    cudaGetSymbolAddress((void**)&X, g_X);
    cudaGetSymbolAddress((void**)&H, g_H);
    cudaGetSymbolAddress((void**)&W1T, g_W1T);
    cudaGetSymbolAddress((void**)&W2T, g_W2T);

    cudaFuncSetAttribute((const void*)hgemm<DIN, true>,
                         cudaFuncAttributeMaxDynamicSharedMemorySize, HGEMM_SMEM);
    cudaFuncSetAttribute((const void*)hgemm<DOUT, false>,
                         cudaFuncAttributeMaxDynamicSharedMemorySize, HGEMM_SMEM);

    prep_all<<<F2H_BLOCKS + PREPW_BLOCKS, 256>>>(feat2, W1, W2);
    knn_interp_kernel<<<NQ / 64, 256>>>(xyz1, xyz2, feat1);

    dim3 grid(DOUT / 128, NQ / 128);
    hgemm<DIN, true><<<grid, 256, HGEMM_SMEM>>>(X, W1T, b1, H, nullptr);
    hgemm<DOUT, false><<<grid, 256, HGEMM_SMEM>>>(H, W2T, b2, nullptr, out);
}